// round 12
// baseline (speedup 1.0000x reference)
#include <cuda_runtime.h>

#define NPTS    4096
#define BATCH   16
#define NCLOUD  (2 * BATCH)          // 32 clouds (pred 0..15, target 16..31)
#define NB      256                  // x-buckets over [-5, 5]
#define INV_BW  (NB / 10.0f)
#define QT      2
#define QPW     64                   // queries per warp
#define MTHREADS 256                 // 8 warps per block
#define QPB     (8 * QPW)            // 512 queries per block
#define QS      (NPTS / QPB)         // 8 query slices
#define PAD     64                   // positional phase-1 floor (points per side)
#define CHUNK   32                   // phase-2 chunk size in groups (128 points)

#define PREP_SMEM (4 * NPTS * 4 + (NB + (NB + 1) + NB) * 4)
#define MIN_SMEM  (NPTS * 12 + (NB + 1) * 4)

// ---- global scratch (static, no allocation) ----
__device__ float  g_sx[NCLOUD][NPTS];          // sorted x (query view)
__device__ float  g_sy[NCLOUD][NPTS];          // sorted y
__device__ float4 g_pk4[NCLOUD][NPTS * 3 / 4]; // prepacked groups of 4 pts:
                                               // [x2*4][y2*4][n*4]
__device__ int    g_off[NCLOUD][NB + 1];       // bucket offsets

__device__ __forceinline__ int bucketof(float x) {
    int b = (int)((x + 5.0f) * INV_BW);
    return min(max(b, 0), NB - 1);
}

__device__ __forceinline__ unsigned long long pack2(float lo, float hi) {
    unsigned long long r;
    asm("mov.b64 %0, {%1, %2};" : "=l"(r) : "f"(lo), "f"(hi));
    return r;
}

// 4 data points x 1 query: 4x fma.rn.f32x2 + min tree, one asm scope.
__device__ __forceinline__ void step4(unsigned long long qx, unsigned long long qy,
                                      unsigned long long xx0, unsigned long long yy0,
                                      unsigned long long nn0,
                                      unsigned long long xx1, unsigned long long yy1,
                                      unsigned long long nn1,
                                      float& mn) {
    asm("{\n\t"
        ".reg .b64 v0, v1;\n\t"
        ".reg .f32 a, b, c, d, r0, r1, t;\n\t"
        "fma.rn.f32x2 v0, %1, %3, %5;\n\t"
        "fma.rn.f32x2 v0, %2, %4, v0;\n\t"
        "fma.rn.f32x2 v1, %1, %6, %8;\n\t"
        "fma.rn.f32x2 v1, %2, %7, v1;\n\t"
        "mov.b64 {a, b}, v0;\n\t"
        "mov.b64 {c, d}, v1;\n\t"
        "min.f32 r0, a, b;\n\t"
        "min.f32 r1, c, d;\n\t"
        "min.f32 t, r0, r1;\n\t"
        "min.f32 %0, %0, t;\n\t"
        "}"
        : "+f"(mn)
        : "l"(qx), "l"(qy), "l"(xx0), "l"(yy0), "l"(nn0),
          "l"(xx1), "l"(yy1), "l"(nn1));
}

// ============================================================================
// Prep: counting-sort each cloud by x-bucket (through smem, coalesced output).
// ============================================================================
__global__ __launch_bounds__(512) void prep_kernel(
    const float* __restrict__ pred,
    const float* __restrict__ target,
    float* __restrict__ out)
{
    extern __shared__ char dyn[];
    float* sx  = (float*)dyn;            // input x
    float* sy  = sx + NPTS;              // input y
    float* ox  = sy + NPTS;              // sorted x
    float* oy  = ox + NPTS;              // sorted y
    int*   cnt = (int*)(oy + NPTS);
    int*   off = cnt + NB;               // NB+1
    int*   woff = off + NB + 1;

    const int c = blockIdx.x;      // cloud id
    const int t = threadIdx.x;
    if (c == 0 && t < 2) out[t] = 0.0f;

    const float2* src = (const float2*)((c < BATCH ? pred : target)
                                        + (size_t)(c & (BATCH - 1)) * NPTS * 2);
    for (int i = t; i < NPTS; i += 512) {
        float2 p = src[i];
        sx[i] = p.x;  sy[i] = p.y;
    }
    if (t < NB) cnt[t] = 0;
    __syncthreads();

    for (int i = t; i < NPTS; i += 512)
        atomicAdd(&cnt[bucketof(sx[i])], 1);
    __syncthreads();

    // exclusive scan of 256 counts: warp 0, 8 buckets per lane
    if (t < 32) {
        int base = t * 8, v[8], s = 0;
#pragma unroll
        for (int k = 0; k < 8; k++) { v[k] = cnt[base + k]; s += v[k]; }
        int incl = s;
#pragma unroll
        for (int o = 1; o < 32; o <<= 1) {
            int n = __shfl_up_sync(0xffffffffu, incl, o);
            if (t >= o) incl += n;
        }
        int run = incl - s;
#pragma unroll
        for (int k = 0; k < 8; k++) { off[base + k] = run; run += v[k]; }
        if (t == 31) off[NB] = run;
    }
    __syncthreads();
    if (t < NB) woff[t] = off[t];
    __syncthreads();

    // scatter into smem (random smem writes, cheap)
    for (int i = t; i < NPTS; i += 512) {
        float x = sx[i], y = sy[i];
        int pos = atomicAdd(&woff[bucketof(x)], 1);
        ox[pos] = x;  oy[pos] = y;
    }
    __syncthreads();

    // coalesced global write-out
    float* pk = (float*)g_pk4[c];
    for (int p = t; p < NPTS; p += 512) {
        float x = ox[p], y = oy[p];
        g_sx[c][p] = x;
        g_sy[c][p] = y;
        int base = (p >> 2) * 12 + (p & 3);
        pk[base]     = -2.0f * x;
        pk[base + 4] = -2.0f * y;
        pk[base + 8] = x * x + y * y;
    }
    for (int i = t; i <= NB; i += 512) g_off[c][i] = off[i];
}

// ============================================================================
// Min: warp = 64 consecutive sorted queries; positional phase 1 + adaptive
// chunked phase 2 (R refreshed per chunk). Dual accumulators for ILP.
// ============================================================================
struct Acc { float a[QT], b[QT]; };   // even/odd group accumulators

__device__ __forceinline__ void scan_range(const ulonglong2* s_pk,
                                           int glo, int ghi,
                                           const unsigned long long* qxx,
                                           const unsigned long long* qyy,
                                           Acc& acc) {
    int g = glo;
#pragma unroll 2
    for (; g + 2 <= ghi; g += 2) {
        ulonglong2 xx0 = s_pk[g * 3 + 0];
        ulonglong2 yy0 = s_pk[g * 3 + 1];
        ulonglong2 nn0 = s_pk[g * 3 + 2];
        ulonglong2 xx1 = s_pk[g * 3 + 3];
        ulonglong2 yy1 = s_pk[g * 3 + 4];
        ulonglong2 nn1 = s_pk[g * 3 + 5];
#pragma unroll
        for (int q = 0; q < QT; q++) {
            step4(qxx[q], qyy[q], xx0.x, yy0.x, nn0.x, xx0.y, yy0.y, nn0.y, acc.a[q]);
            step4(qxx[q], qyy[q], xx1.x, yy1.x, nn1.x, xx1.y, yy1.y, nn1.y, acc.b[q]);
        }
    }
    if (g < ghi) {
        ulonglong2 xx = s_pk[g * 3 + 0];
        ulonglong2 yy = s_pk[g * 3 + 1];
        ulonglong2 nn = s_pk[g * 3 + 2];
#pragma unroll
        for (int q = 0; q < QT; q++)
            step4(qxx[q], qyy[q], xx.x, yy.x, nn.x, xx.y, yy.y, nn.y, acc.a[q]);
    }
}

__global__ __launch_bounds__(MTHREADS, 2) void chamfer_min_kernel(float* __restrict__ out)
{
    extern __shared__ char dyn[];
    ulonglong2* s_pk = (ulonglong2*)dyn;            // 3072 entries, 48 KB
    int* soff = (int*)(dyn + NPTS * 12);            // NB+1

    const int dir = blockIdx.z;
    const int b   = blockIdx.y;
    const int qs  = blockIdx.x;
    const int wid  = threadIdx.x >> 5;
    const int lane = threadIdx.x & 31;

    const int qcloud = (dir == 0) ? b : (BATCH + b);
    const int dcloud = (dir == 0) ? (BATCH + b) : b;

    // cache the whole prepacked data cloud in smem (coalesced 48 KB copy)
    {
        const float4* gp = g_pk4[dcloud];
        float4* sp = (float4*)dyn;
        for (int i = threadIdx.x; i < NPTS * 3 / 4; i += MTHREADS)
            sp[i] = gp[i];
        for (int i = threadIdx.x; i <= NB; i += MTHREADS)
            soff[i] = g_off[dcloud][i];
    }
    __syncthreads();

    const int q0 = qs * QPB + wid * QPW;

    unsigned long long qxx[QT], qyy[QT];
    float pn[QT], qxs[QT];
    Acc acc;
#pragma unroll
    for (int k = 0; k < QT; k++) {
        int qi = q0 + k * 32 + lane;              // sorted ascending
        float x = g_sx[qcloud][qi];
        float y = g_sy[qcloud][qi];
        qxs[k] = x;
        qxx[k] = pack2(x, x);
        qyy[k] = pack2(y, y);
        pn[k]  = x * x + y * y;
        acc.a[k] = 3.4e38f;
        acc.b[k] = 3.4e38f;
    }
    const float qminx = __shfl_sync(0xffffffffu, qxs[0], 0);
    const float qmaxx = __shfl_sync(0xffffffffu, qxs[QT - 1], 31);

    // phase 1: home bucket range +-1, widened positionally by PAD per side
    const int b1lo = max(bucketof(qminx) - 1, 0);
    const int b1hi = min(bucketof(qmaxx) + 1, NB - 1);
    const int p1lo = max(soff[b1lo] - PAD, 0);
    const int p1hi = min(soff[b1hi + 1] + PAD, NPTS);
    int lo = p1lo >> 2, hi = (p1hi + 3) >> 2;     // current window, group units
    scan_range(s_pk, lo, hi, qxx, qyy, acc);

    // phase 2: adaptive chunked outward scan; R refreshed after every chunk.
    for (;;) {
        float m = fmaxf(acc.a[0], acc.b[0]) + pn[0];
#pragma unroll
        for (int k = 1; k < QT; k++)
            m = fmaxf(m, fmaxf(acc.a[k], acc.b[k]) + pn[k]);
#pragma unroll
        for (int o = 16; o; o >>= 1)
            m = fmaxf(m, __shfl_xor_sync(0xffffffffu, m, o));
        const float R = sqrtf(fmaxf(m, 0.0f));

        const int tlo = soff[bucketof(qminx - R)] >> 2;
        const int thi = (soff[bucketof(qmaxx + R) + 1] + 3) >> 2;
        const bool needL = tlo < lo, needR = thi > hi;
        if (!needL && !needR) break;
        if (needL) {
            int nl = max(tlo, lo - CHUNK);
            scan_range(s_pk, nl, lo, qxx, qyy, acc);
            lo = nl;
        }
        if (needR) {
            int nh = min(thi, hi + CHUNK);
            scan_range(s_pk, hi, nh, qxx, qyy, acc);
            hi = nh;
        }
    }

    // per-warp sum, one atomic
    float val = 0.0f;
#pragma unroll
    for (int k = 0; k < QT; k++)
        val += fminf(acc.a[k], acc.b[k]) + pn[k];
#pragma unroll
    for (int o = 16; o; o >>= 1)
        val += __shfl_xor_sync(0xffffffffu, val, o);
    if (lane == 0)
        atomicAdd(&out[dir], val * (1.0f / (float)(NPTS * BATCH)));
}

extern "C" void kernel_launch(void* const* d_in, const int* in_sizes, int n_in,
                              void* d_out, int out_size) {
    const float* pred   = (const float*)d_in[0];
    const float* target = (const float*)d_in[1];
    float* out = (float*)d_out;

    cudaFuncSetAttribute(prep_kernel,
                         cudaFuncAttributeMaxDynamicSharedMemorySize, PREP_SMEM);
    cudaFuncSetAttribute(chamfer_min_kernel,
                         cudaFuncAttributeMaxDynamicSharedMemorySize, MIN_SMEM);

    prep_kernel<<<NCLOUD, 512, PREP_SMEM>>>(pred, target, out);

    dim3 grid(QS, BATCH, 2);                      // 8 x 16 x 2 = 256 blocks
    chamfer_min_kernel<<<grid, MTHREADS, MIN_SMEM>>>(out);
}

// round 13
// speedup vs baseline: 1.2869x; 1.2869x over previous
#include <cuda_runtime.h>

#define NPTS    4096
#define BATCH   16
#define NCLOUD  (2 * BATCH)          // 32 clouds (pred 0..15, target 16..31)
#define NB      256                  // x-buckets over [-5, 5]
#define INV_BW  (NB / 10.0f)
#define QT      1
#define QPW     32                   // queries per warp (one per lane)
#define MTHREADS 256                 // 8 warps per block
#define QPB     (8 * QPW)            // 256 queries per block
#define QS      (NPTS / QPB)         // 16 query slices
#define PAD     64                   // positional phase-1 floor (points per side)
#define CHUNK   32                   // phase-2 chunk size in groups (128 points)

#define PREP_SMEM (4 * NPTS * 4 + (NB + (NB + 1) + NB) * 4)
#define MIN_SMEM  (NPTS * 12 + (NB + 1) * 4)

// ---- global scratch (static, no allocation) ----
__device__ float  g_sx[NCLOUD][NPTS];          // sorted x (query view)
__device__ float  g_sy[NCLOUD][NPTS];          // sorted y
__device__ float4 g_pk4[NCLOUD][NPTS * 3 / 4]; // prepacked groups of 4 pts:
                                               // [x2*4][y2*4][n*4]
__device__ int    g_off[NCLOUD][NB + 1];       // bucket offsets

__device__ __forceinline__ int bucketof(float x) {
    int b = (int)((x + 5.0f) * INV_BW);
    return min(max(b, 0), NB - 1);
}

__device__ __forceinline__ unsigned long long pack2(float lo, float hi) {
    unsigned long long r;
    asm("mov.b64 %0, {%1, %2};" : "=l"(r) : "f"(lo), "f"(hi));
    return r;
}

// 4 data points x 1 query: 4x fma.rn.f32x2 + min tree, one asm scope.
__device__ __forceinline__ void step4(unsigned long long qx, unsigned long long qy,
                                      unsigned long long xx0, unsigned long long yy0,
                                      unsigned long long nn0,
                                      unsigned long long xx1, unsigned long long yy1,
                                      unsigned long long nn1,
                                      float& mn) {
    asm("{\n\t"
        ".reg .b64 v0, v1;\n\t"
        ".reg .f32 a, b, c, d, r0, r1, t;\n\t"
        "fma.rn.f32x2 v0, %1, %3, %5;\n\t"
        "fma.rn.f32x2 v0, %2, %4, v0;\n\t"
        "fma.rn.f32x2 v1, %1, %6, %8;\n\t"
        "fma.rn.f32x2 v1, %2, %7, v1;\n\t"
        "mov.b64 {a, b}, v0;\n\t"
        "mov.b64 {c, d}, v1;\n\t"
        "min.f32 r0, a, b;\n\t"
        "min.f32 r1, c, d;\n\t"
        "min.f32 t, r0, r1;\n\t"
        "min.f32 %0, %0, t;\n\t"
        "}"
        : "+f"(mn)
        : "l"(qx), "l"(qy), "l"(xx0), "l"(yy0), "l"(nn0),
          "l"(xx1), "l"(yy1), "l"(nn1));
}

// ============================================================================
// Prep: counting-sort each cloud by x-bucket (through smem, coalesced output).
// ============================================================================
__global__ __launch_bounds__(512) void prep_kernel(
    const float* __restrict__ pred,
    const float* __restrict__ target,
    float* __restrict__ out)
{
    extern __shared__ char dyn[];
    float* sx  = (float*)dyn;            // input x
    float* sy  = sx + NPTS;              // input y
    float* ox  = sy + NPTS;              // sorted x
    float* oy  = ox + NPTS;              // sorted y
    int*   cnt = (int*)(oy + NPTS);
    int*   off = cnt + NB;               // NB+1
    int*   woff = off + NB + 1;

    const int c = blockIdx.x;      // cloud id
    const int t = threadIdx.x;
    if (c == 0 && t < 2) out[t] = 0.0f;

    const float2* src = (const float2*)((c < BATCH ? pred : target)
                                        + (size_t)(c & (BATCH - 1)) * NPTS * 2);
    for (int i = t; i < NPTS; i += 512) {
        float2 p = src[i];
        sx[i] = p.x;  sy[i] = p.y;
    }
    if (t < NB) cnt[t] = 0;
    __syncthreads();

    for (int i = t; i < NPTS; i += 512)
        atomicAdd(&cnt[bucketof(sx[i])], 1);
    __syncthreads();

    // exclusive scan of 256 counts: warp 0, 8 buckets per lane
    if (t < 32) {
        int base = t * 8, v[8], s = 0;
#pragma unroll
        for (int k = 0; k < 8; k++) { v[k] = cnt[base + k]; s += v[k]; }
        int incl = s;
#pragma unroll
        for (int o = 1; o < 32; o <<= 1) {
            int n = __shfl_up_sync(0xffffffffu, incl, o);
            if (t >= o) incl += n;
        }
        int run = incl - s;
#pragma unroll
        for (int k = 0; k < 8; k++) { off[base + k] = run; run += v[k]; }
        if (t == 31) off[NB] = run;
    }
    __syncthreads();
    if (t < NB) woff[t] = off[t];
    __syncthreads();

    // scatter into smem (random smem writes, cheap)
    for (int i = t; i < NPTS; i += 512) {
        float x = sx[i], y = sy[i];
        int pos = atomicAdd(&woff[bucketof(x)], 1);
        ox[pos] = x;  oy[pos] = y;
    }
    __syncthreads();

    // coalesced global write-out
    float* pk = (float*)g_pk4[c];
    for (int p = t; p < NPTS; p += 512) {
        float x = ox[p], y = oy[p];
        g_sx[c][p] = x;
        g_sy[c][p] = y;
        int base = (p >> 2) * 12 + (p & 3);
        pk[base]     = -2.0f * x;
        pk[base + 4] = -2.0f * y;
        pk[base + 8] = x * x + y * y;
    }
    for (int i = t; i <= NB; i += 512) g_off[c][i] = off[i];
}

// ============================================================================
// Min: warp = 32 consecutive sorted queries (1/lane); positional phase 1 +
// adaptive chunked phase 2 (R refreshed per chunk). Dual accumulators for ILP.
// ============================================================================
__device__ __forceinline__ void scan_range(const ulonglong2* s_pk,
                                           int glo, int ghi,
                                           unsigned long long qx,
                                           unsigned long long qy,
                                           float& ma, float& mb) {
    int g = glo;
#pragma unroll 2
    for (; g + 2 <= ghi; g += 2) {
        ulonglong2 xx0 = s_pk[g * 3 + 0];
        ulonglong2 yy0 = s_pk[g * 3 + 1];
        ulonglong2 nn0 = s_pk[g * 3 + 2];
        ulonglong2 xx1 = s_pk[g * 3 + 3];
        ulonglong2 yy1 = s_pk[g * 3 + 4];
        ulonglong2 nn1 = s_pk[g * 3 + 5];
        step4(qx, qy, xx0.x, yy0.x, nn0.x, xx0.y, yy0.y, nn0.y, ma);
        step4(qx, qy, xx1.x, yy1.x, nn1.x, xx1.y, yy1.y, nn1.y, mb);
    }
    if (g < ghi) {
        ulonglong2 xx = s_pk[g * 3 + 0];
        ulonglong2 yy = s_pk[g * 3 + 1];
        ulonglong2 nn = s_pk[g * 3 + 2];
        step4(qx, qy, xx.x, yy.x, nn.x, xx.y, yy.y, nn.y, ma);
    }
}

__global__ __launch_bounds__(MTHREADS, 4) void chamfer_min_kernel(float* __restrict__ out)
{
    extern __shared__ char dyn[];
    ulonglong2* s_pk = (ulonglong2*)dyn;            // 3072 entries, 48 KB
    int* soff = (int*)(dyn + NPTS * 12);            // NB+1

    const int dir = blockIdx.z;
    const int b   = blockIdx.y;
    const int qs  = blockIdx.x;
    const int wid  = threadIdx.x >> 5;
    const int lane = threadIdx.x & 31;

    const int qcloud = (dir == 0) ? b : (BATCH + b);
    const int dcloud = (dir == 0) ? (BATCH + b) : b;

    // cache the whole prepacked data cloud in smem (coalesced 48 KB copy)
    {
        const float4* gp = g_pk4[dcloud];
        float4* sp = (float4*)dyn;
        for (int i = threadIdx.x; i < NPTS * 3 / 4; i += MTHREADS)
            sp[i] = gp[i];
        for (int i = threadIdx.x; i <= NB; i += MTHREADS)
            soff[i] = g_off[dcloud][i];
    }
    __syncthreads();

    const int qi = qs * QPB + wid * QPW + lane;   // sorted ascending

    const float x = g_sx[qcloud][qi];
    const float y = g_sy[qcloud][qi];
    const unsigned long long qx = pack2(x, x);
    const unsigned long long qy = pack2(y, y);
    const float pn = x * x + y * y;
    float ma = 3.4e38f, mb = 3.4e38f;

    const float qminx = __shfl_sync(0xffffffffu, x, 0);
    const float qmaxx = __shfl_sync(0xffffffffu, x, 31);

    // phase 1: home bucket range +-1, widened positionally by PAD per side
    const int b1lo = max(bucketof(qminx) - 1, 0);
    const int b1hi = min(bucketof(qmaxx) + 1, NB - 1);
    const int p1lo = max(soff[b1lo] - PAD, 0);
    const int p1hi = min(soff[b1hi + 1] + PAD, NPTS);
    int lo = p1lo >> 2, hi = (p1hi + 3) >> 2;     // current window, group units
    scan_range(s_pk, lo, hi, qx, qy, ma, mb);

    // phase 2: adaptive chunked outward scan; R refreshed after every chunk.
    for (;;) {
        float m = fminf(ma, mb) + pn;
#pragma unroll
        for (int o = 16; o; o >>= 1)
            m = fmaxf(m, __shfl_xor_sync(0xffffffffu, m, o));
        const float R = sqrtf(fmaxf(m, 0.0f));

        const int tlo = soff[bucketof(qminx - R)] >> 2;
        const int thi = (soff[bucketof(qmaxx + R) + 1] + 3) >> 2;
        const bool needL = tlo < lo, needR = thi > hi;
        if (!needL && !needR) break;
        if (needL) {
            int nl = max(tlo, lo - CHUNK);
            scan_range(s_pk, nl, lo, qx, qy, ma, mb);
            lo = nl;
        }
        if (needR) {
            int nh = min(thi, hi + CHUNK);
            scan_range(s_pk, hi, nh, qx, qy, ma, mb);
            hi = nh;
        }
    }

    // per-warp sum, one atomic
    float val = fminf(ma, mb) + pn;
#pragma unroll
    for (int o = 16; o; o >>= 1)
        val += __shfl_xor_sync(0xffffffffu, val, o);
    if (lane == 0)
        atomicAdd(&out[dir], val * (1.0f / (float)(NPTS * BATCH)));
}

extern "C" void kernel_launch(void* const* d_in, const int* in_sizes, int n_in,
                              void* d_out, int out_size) {
    const float* pred   = (const float*)d_in[0];
    const float* target = (const float*)d_in[1];
    float* out = (float*)d_out;

    cudaFuncSetAttribute(prep_kernel,
                         cudaFuncAttributeMaxDynamicSharedMemorySize, PREP_SMEM);
    cudaFuncSetAttribute(chamfer_min_kernel,
                         cudaFuncAttributeMaxDynamicSharedMemorySize, MIN_SMEM);

    prep_kernel<<<NCLOUD, 512, PREP_SMEM>>>(pred, target, out);

    dim3 grid(QS, BATCH, 2);                      // 16 x 16 x 2 = 512 blocks
    chamfer_min_kernel<<<grid, MTHREADS, MIN_SMEM>>>(out);
}

// round 14
// speedup vs baseline: 1.2962x; 1.0072x over previous
#include <cuda_runtime.h>

#define NPTS    4096
#define BATCH   16
#define NCLOUD  (2 * BATCH)          // 32 clouds (pred 0..15, target 16..31)
#define NB      256                  // x-buckets over [-5, 5]
#define INV_BW  (NB / 10.0f)
#define QPW     32                   // queries per warp (one per lane)
#define MTHREADS 256                 // 8 warps per block
#define QPB     (8 * QPW)            // 256 queries per block
#define QS      (NPTS / QPB)         // 16 query slices
#define PAD     64                   // positional phase-1 floor (points per side)
#define CHUNK   64                   // phase-2 chunk size in groups (256 points)

#define PREP_SMEM (4 * NPTS * 4 + (NB + (NB + 1) + NB) * 4)
#define MIN_SMEM  (NPTS * 12 + (NB + 1) * 4)

// ---- global scratch (static, no allocation) ----
__device__ float  g_sx[NCLOUD][NPTS];          // sorted x (query view)
__device__ float  g_sy[NCLOUD][NPTS];          // sorted y
__device__ float4 g_pk4[NCLOUD][NPTS * 3 / 4]; // prepacked groups of 4 pts:
                                               // [x2*4][y2*4][n*4]
__device__ int    g_off[NCLOUD][NB + 1];       // bucket offsets

// heavy-first qs order: extremes of the sorted axis first
__constant__ int c_qsmap[QS] = {0, 15, 1, 14, 2, 13, 3, 12,
                                4, 11, 5, 10, 6, 9, 7, 8};

__device__ __forceinline__ int bucketof(float x) {
    int b = (int)((x + 5.0f) * INV_BW);
    return min(max(b, 0), NB - 1);
}

__device__ __forceinline__ unsigned long long pack2(float lo, float hi) {
    unsigned long long r;
    asm("mov.b64 %0, {%1, %2};" : "=l"(r) : "f"(lo), "f"(hi));
    return r;
}

// 4 data points x 1 query: 4x fma.rn.f32x2 + min tree, one asm scope.
__device__ __forceinline__ void step4(unsigned long long qx, unsigned long long qy,
                                      unsigned long long xx0, unsigned long long yy0,
                                      unsigned long long nn0,
                                      unsigned long long xx1, unsigned long long yy1,
                                      unsigned long long nn1,
                                      float& mn) {
    asm("{\n\t"
        ".reg .b64 v0, v1;\n\t"
        ".reg .f32 a, b, c, d, r0, r1, t;\n\t"
        "fma.rn.f32x2 v0, %1, %3, %5;\n\t"
        "fma.rn.f32x2 v0, %2, %4, v0;\n\t"
        "fma.rn.f32x2 v1, %1, %6, %8;\n\t"
        "fma.rn.f32x2 v1, %2, %7, v1;\n\t"
        "mov.b64 {a, b}, v0;\n\t"
        "mov.b64 {c, d}, v1;\n\t"
        "min.f32 r0, a, b;\n\t"
        "min.f32 r1, c, d;\n\t"
        "min.f32 t, r0, r1;\n\t"
        "min.f32 %0, %0, t;\n\t"
        "}"
        : "+f"(mn)
        : "l"(qx), "l"(qy), "l"(xx0), "l"(yy0), "l"(nn0),
          "l"(xx1), "l"(yy1), "l"(nn1));
}

// ============================================================================
// Prep: counting-sort each cloud by x-bucket (through smem, coalesced output).
// ============================================================================
__global__ __launch_bounds__(512) void prep_kernel(
    const float* __restrict__ pred,
    const float* __restrict__ target,
    float* __restrict__ out)
{
    extern __shared__ char dyn[];
    float* sx  = (float*)dyn;            // input x
    float* sy  = sx + NPTS;              // input y
    float* ox  = sy + NPTS;              // sorted x
    float* oy  = ox + NPTS;              // sorted y
    int*   cnt = (int*)(oy + NPTS);
    int*   off = cnt + NB;               // NB+1
    int*   woff = off + NB + 1;

    const int c = blockIdx.x;      // cloud id
    const int t = threadIdx.x;
    if (c == 0 && t < 2) out[t] = 0.0f;

    const float2* src = (const float2*)((c < BATCH ? pred : target)
                                        + (size_t)(c & (BATCH - 1)) * NPTS * 2);
    for (int i = t; i < NPTS; i += 512) {
        float2 p = src[i];
        sx[i] = p.x;  sy[i] = p.y;
    }
    if (t < NB) cnt[t] = 0;
    __syncthreads();

    for (int i = t; i < NPTS; i += 512)
        atomicAdd(&cnt[bucketof(sx[i])], 1);
    __syncthreads();

    // exclusive scan of 256 counts: warp 0, 8 buckets per lane
    if (t < 32) {
        int base = t * 8, v[8], s = 0;
#pragma unroll
        for (int k = 0; k < 8; k++) { v[k] = cnt[base + k]; s += v[k]; }
        int incl = s;
#pragma unroll
        for (int o = 1; o < 32; o <<= 1) {
            int n = __shfl_up_sync(0xffffffffu, incl, o);
            if (t >= o) incl += n;
        }
        int run = incl - s;
#pragma unroll
        for (int k = 0; k < 8; k++) { off[base + k] = run; run += v[k]; }
        if (t == 31) off[NB] = run;
    }
    __syncthreads();
    if (t < NB) woff[t] = off[t];
    __syncthreads();

    // scatter into smem (random smem writes, cheap)
    for (int i = t; i < NPTS; i += 512) {
        float x = sx[i], y = sy[i];
        int pos = atomicAdd(&woff[bucketof(x)], 1);
        ox[pos] = x;  oy[pos] = y;
    }
    __syncthreads();

    // coalesced global write-out
    float* pk = (float*)g_pk4[c];
    for (int p = t; p < NPTS; p += 512) {
        float x = ox[p], y = oy[p];
        g_sx[c][p] = x;
        g_sy[c][p] = y;
        int base = (p >> 2) * 12 + (p & 3);
        pk[base]     = -2.0f * x;
        pk[base + 4] = -2.0f * y;
        pk[base + 8] = x * x + y * y;
    }
    for (int i = t; i <= NB; i += 512) g_off[c][i] = off[i];
}

// ============================================================================
// Min: warp = 32 consecutive sorted queries (1/lane); positional phase 1 +
// adaptive chunked phase 2. Software-pipelined scan (prefetch next group).
// ============================================================================
__device__ __forceinline__ void scan_range(const ulonglong2* s_pk,
                                           int glo, int ghi,
                                           unsigned long long qx,
                                           unsigned long long qy,
                                           float& ma, float& mb) {
    if (glo >= ghi) return;
    // prologue: load group glo
    ulonglong2 xx = s_pk[glo * 3 + 0];
    ulonglong2 yy = s_pk[glo * 3 + 1];
    ulonglong2 nn = s_pk[glo * 3 + 2];
#pragma unroll 4
    for (int g = glo + 1; g < ghi; g++) {
        // prefetch next group while computing current
        ulonglong2 xx1 = s_pk[g * 3 + 0];
        ulonglong2 yy1 = s_pk[g * 3 + 1];
        ulonglong2 nn1 = s_pk[g * 3 + 2];
        step4(qx, qy, xx.x, yy.x, nn.x, xx.y, yy.y, nn.y,
              ((g - glo) & 1) ? ma : mb);
        xx = xx1; yy = yy1; nn = nn1;
    }
    step4(qx, qy, xx.x, yy.x, nn.x, xx.y, yy.y, nn.y, ma);
}

__global__ __launch_bounds__(MTHREADS, 3) void chamfer_min_kernel(float* __restrict__ out)
{
    extern __shared__ char dyn[];
    ulonglong2* s_pk = (ulonglong2*)dyn;            // 3072 entries, 48 KB
    int* soff = (int*)(dyn + NPTS * 12);            // NB+1

    const int dir = blockIdx.z;
    const int b   = blockIdx.y;
    const int qs  = c_qsmap[blockIdx.x];            // heavy-first order
    const int wid  = threadIdx.x >> 5;
    const int lane = threadIdx.x & 31;

    const int qcloud = (dir == 0) ? b : (BATCH + b);
    const int dcloud = (dir == 0) ? (BATCH + b) : b;

    // cache the whole prepacked data cloud in smem (coalesced 48 KB copy)
    {
        const float4* gp = g_pk4[dcloud];
        float4* sp = (float4*)dyn;
        for (int i = threadIdx.x; i < NPTS * 3 / 4; i += MTHREADS)
            sp[i] = gp[i];
        for (int i = threadIdx.x; i <= NB; i += MTHREADS)
            soff[i] = g_off[dcloud][i];
    }
    __syncthreads();

    const int qi = qs * QPB + wid * QPW + lane;   // sorted ascending

    const float x = g_sx[qcloud][qi];
    const float y = g_sy[qcloud][qi];
    const unsigned long long qx = pack2(x, x);
    const unsigned long long qy = pack2(y, y);
    const float pn = x * x + y * y;
    float ma = 3.4e38f, mb = 3.4e38f;

    const float qminx = __shfl_sync(0xffffffffu, x, 0);
    const float qmaxx = __shfl_sync(0xffffffffu, x, 31);

    // phase 1: home bucket range +-1, widened positionally by PAD per side
    const int b1lo = max(bucketof(qminx) - 1, 0);
    const int b1hi = min(bucketof(qmaxx) + 1, NB - 1);
    const int p1lo = max(soff[b1lo] - PAD, 0);
    const int p1hi = min(soff[b1hi + 1] + PAD, NPTS);
    int lo = p1lo >> 2, hi = (p1hi + 3) >> 2;     // current window, group units
    scan_range(s_pk, lo, hi, qx, qy, ma, mb);

    // phase 2: adaptive chunked outward scan; R refreshed after every chunk.
    for (;;) {
        float m = fminf(ma, mb) + pn;
#pragma unroll
        for (int o = 16; o; o >>= 1)
            m = fmaxf(m, __shfl_xor_sync(0xffffffffu, m, o));
        const float R = sqrtf(fmaxf(m, 0.0f));

        const int tlo = soff[bucketof(qminx - R)] >> 2;
        const int thi = (soff[bucketof(qmaxx + R) + 1] + 3) >> 2;
        const bool needL = tlo < lo, needR = thi > hi;
        if (!needL && !needR) break;
        if (needL) {
            int nl = max(tlo, lo - CHUNK);
            scan_range(s_pk, nl, lo, qx, qy, ma, mb);
            lo = nl;
        }
        if (needR) {
            int nh = min(thi, hi + CHUNK);
            scan_range(s_pk, hi, nh, qx, qy, ma, mb);
            hi = nh;
        }
    }

    // per-warp sum, one atomic
    float val = fminf(ma, mb) + pn;
#pragma unroll
    for (int o = 16; o; o >>= 1)
        val += __shfl_xor_sync(0xffffffffu, val, o);
    if (lane == 0)
        atomicAdd(&out[dir], val * (1.0f / (float)(NPTS * BATCH)));
}

extern "C" void kernel_launch(void* const* d_in, const int* in_sizes, int n_in,
                              void* d_out, int out_size) {
    const float* pred   = (const float*)d_in[0];
    const float* target = (const float*)d_in[1];
    float* out = (float*)d_out;

    cudaFuncSetAttribute(prep_kernel,
                         cudaFuncAttributeMaxDynamicSharedMemorySize, PREP_SMEM);
    cudaFuncSetAttribute(chamfer_min_kernel,
                         cudaFuncAttributeMaxDynamicSharedMemorySize, MIN_SMEM);

    prep_kernel<<<NCLOUD, 512, PREP_SMEM>>>(pred, target, out);

    dim3 grid(QS, BATCH, 2);                      // 16 x 16 x 2 = 512 blocks
    chamfer_min_kernel<<<grid, MTHREADS, MIN_SMEM>>>(out);
}